// round 3
// baseline (speedup 1.0000x reference)
#include <cuda_runtime.h>
#include <cuda_bf16.h>
#include <math.h>

// Eikonal loss, single fused persistent kernel.
// (B,1,H,W) = (64,1,512,512) fp32 -> 1 fp32 scalar.

#define H 512
#define W 512
#define W4 (W / 4)
#define ROWS 8                 // rows per work item strip
#define THREADS 256
#define GRID_BLOCKS 740        // 148 SMs * 5 blocks
#define MAX_BLOCKS 4096

__device__ float2 g_part[MAX_BLOCKS];
__device__ unsigned int g_ticket;   // zero-init at load; last block resets to 0

__device__ __forceinline__ float sqrt_approx(float x) {
    float r;
    asm("sqrt.approx.f32 %0, %1;" : "=f"(r) : "f"(x));
    return r;
}

// Load 6-wide window (x-1 .. x+4, clamped) from a row, emit scaled S and D.
__device__ __forceinline__ void load_row_sd(const float* __restrict__ row,
                                            int x, int xl, int xr,
                                            float* __restrict__ S,
                                            float* __restrict__ D) {
    float4 v = *(const float4*)(row + x);
    float w0 = __ldg(row + xl);
    float w5 = __ldg(row + xr);
    float w[6] = {w0, v.x, v.y, v.z, v.w, w5};
    #pragma unroll
    for (int j = 0; j < 4; j++) {
        D[j] = (w[j + 2] - w[j]) * 0.125f;
        S[j] = fmaf(2.0f, w[j + 1], w[j] + w[j + 2]) * 0.125f;
    }
}

__global__ void __launch_bounds__(THREADS, 5) eik_fused_kernel(
    const float* __restrict__ pred,
    const float* __restrict__ reach,
    float* __restrict__ out,
    int nItems2,   // total (b,strip) pairs / 2
    int nBlocks)
{
    const int x4i  = threadIdx.x & (W4 - 1);
    const int half = threadIdx.x >> 7;       // 0/1: which item of the pair

    const int x  = x4i * 4;
    const int xl = (x > 0) ? (x - 1) : 0;
    const int xr = (x + 4 < W) ? (x + 4) : (W - 1);

    const int STRIPS = H / ROWS;             // 64

    float lsum = 0.0f;
    float lcnt = 0.0f;

    for (int item2 = blockIdx.x; item2 < nItems2; item2 += gridDim.x) {
        const int item  = item2 * 2 + half;  // global (b,strip) index
        const int b     = item / STRIPS;
        const int strip = item - b * STRIPS;
        const int y0    = strip * ROWS;

        const size_t base = (size_t)b * H * W;
        const float* p = pred + base;
        const float* r = reach + base;

        // rolling scaled row-features: index 0=top, 1=mid, 2=bottom
        float S0[4], S1[4], S2[4], D0[4], D1[4], D2[4];

        {
            const int yT = (y0 > 0) ? (y0 - 1) : 0;
            load_row_sd(p + (size_t)yT * W, x, xl, xr, S0, D0);
            load_row_sd(p + (size_t)y0 * W, x, xl, xr, S1, D1);
        }

        #pragma unroll
        for (int i = 0; i < ROWS; i++) {
            const int y  = y0 + i;
            const int yB = (y < H - 1) ? (y + 1) : (H - 1);
            load_row_sd(p + (size_t)yB * W, x, xl, xr, S2, D2);

            float4 rr = *(const float4*)(r + (size_t)y * W + x);
            const float rv[4] = {rr.x, rr.y, rr.z, rr.w};

            #pragma unroll
            for (int j = 0; j < 4; j++) {
                float gx = fmaf(2.0f, D1[j], D0[j] + D2[j]);
                float gy = S2[j] - S0[j];
                float g2 = fmaf(gx, gx, fmaf(gy, gy, 1e-8f));
                float mag = sqrt_approx(g2);
                float viol = fabsf(mag - 1.0f);
                float msk = (rv[j] > 0.5f) ? 1.0f : 0.0f;
                lsum = fmaf(viol, msk, lsum);
                lcnt += msk;
            }

            #pragma unroll
            for (int j = 0; j < 4; j++) {
                S0[j] = S1[j]; S1[j] = S2[j];
                D0[j] = D1[j]; D1[j] = D2[j];
            }
        }
    }

    // ---- block reduction ----
    #pragma unroll
    for (int off = 16; off > 0; off >>= 1) {
        lsum += __shfl_down_sync(0xFFFFFFFFu, lsum, off);
        lcnt += __shfl_down_sync(0xFFFFFFFFu, lcnt, off);
    }

    __shared__ float s_sum[8];
    __shared__ float s_cnt[8];
    const int lane = threadIdx.x & 31;
    const int wid  = threadIdx.x >> 5;
    if (lane == 0) { s_sum[wid] = lsum; s_cnt[wid] = lcnt; }
    __syncthreads();

    __shared__ bool s_last;
    if (wid == 0) {
        lsum = (lane < 8) ? s_sum[lane] : 0.0f;
        lcnt = (lane < 8) ? s_cnt[lane] : 0.0f;
        #pragma unroll
        for (int off = 4; off > 0; off >>= 1) {
            lsum += __shfl_down_sync(0xFFFFFFFFu, lsum, off);
            lcnt += __shfl_down_sync(0xFFFFFFFFu, lcnt, off);
        }
        if (lane == 0) {
            g_part[blockIdx.x] = make_float2(lsum, lcnt);
            __threadfence();
            unsigned int prev = atomicAdd(&g_ticket, 1u);
            s_last = (prev == (unsigned int)(nBlocks - 1));
        }
    }
    __syncthreads();

    // ---- last block: reduce partials, write output, reset ticket ----
    if (s_last) {
        float fs = 0.0f, fc = 0.0f;
        for (int i = threadIdx.x; i < nBlocks; i += THREADS) {
            float2 v = g_part[i];
            fs += v.x;
            fc += v.y;
        }
        #pragma unroll
        for (int off = 16; off > 0; off >>= 1) {
            fs += __shfl_down_sync(0xFFFFFFFFu, fs, off);
            fc += __shfl_down_sync(0xFFFFFFFFu, fc, off);
        }
        if (lane == 0) { s_sum[wid] = fs; s_cnt[wid] = fc; }
        __syncthreads();
        if (threadIdx.x == 0) {
            fs = 0.0f; fc = 0.0f;
            #pragma unroll
            for (int i = 0; i < THREADS / 32; i++) { fs += s_sum[i]; fc += s_cnt[i]; }
            out[0] = fs / fmaxf(fc, 1.0f);
            g_ticket = 0;   // reset for next graph replay
        }
    }
}

extern "C" void kernel_launch(void* const* d_in, const int* in_sizes, int n_in,
                              void* d_out, int out_size) {
    const float* pred  = (const float*)d_in[0];
    const float* reach = (const float*)d_in[1];
    float* out = (float*)d_out;

    const int total   = in_sizes[0];                // B*H*W
    const int nItems  = total / (W * ROWS);         // B * STRIPS
    const int nItems2 = nItems / 2;                 // pairs per block-iter

    int blocks = GRID_BLOCKS;
    if (blocks > nItems2) blocks = nItems2;

    eik_fused_kernel<<<blocks, THREADS>>>(pred, reach, out, nItems2, blocks);
}